// round 16
// baseline (speedup 1.0000x reference)
#include <cuda_runtime.h>
#include <cstdint>

// LIF scan, smem-staged + time-chunked for occupancy.
// x, out: [rows=524288][T=100] fp32, time contiguous.
// R5 kernel (full-row staging, 432B smem/row) was occupancy-limited to
// 16 warps/SM (occ 24%, DRAM 59%). Chunk T into 52+48 so smem/row halves
// to 208B -> 16 CTAs/SM (32 warps), membrane potential v carried in a
// register across chunks. Stride 52 floats keeps LDS/STS.128 conflict-free
// and makes phase-1/3 smem addressing exactly linear (52 = 13 float4).

static constexpr int T = 100;
static constexpr int T4 = T / 4;            // 25 float4 per row
static constexpr int ROWS_PER_CTA = 64;
static constexpr int STRIDE_F = 52;         // smem row stride in floats
static constexpr float DECAY = 0.5f;        // 1 - 1/TAU, TAU=2
static constexpr float V_TH = 0.5f;

// One chunk: gmem->smem (coalesced), scan in place, smem->gmem (coalesced).
// N4 = float4 count of this chunk (13 or 12), BASE4 = float4 offset in row.
template <int N4, int BASE4>
__device__ __forceinline__ void process_chunk(
    const float4* __restrict__ gsrc,   // tile base as float4 (row-major, 25/row)
    float4* __restrict__ gdst,
    float* __restrict__ tile,          // smem, ROWS_PER_CTA x STRIDE_F floats
    int tid, float& v)
{
    // Phase 1: coalesced load. fidx enumerates (row, col4) of this chunk.
#pragma unroll
    for (int k = 0; k < N4; ++k) {
        int fidx = tid + k * ROWS_PER_CTA;
        int r = fidx / N4;
        int c = fidx % N4;
        float4 d = gsrc[(size_t)r * T4 + BASE4 + c];
        *reinterpret_cast<float4*>(&tile[r * STRIDE_F + c * 4]) = d;
    }
    __syncthreads();

    // Phase 2: per-thread scan of own row, in place.
    {
        float* rowp = &tile[tid * STRIDE_F];
#pragma unroll
        for (int i = 0; i < N4; ++i) {
            float4 xi = *reinterpret_cast<const float4*>(&rowp[i * 4]);
            float4 s;

            v = fmaf(v, DECAY, xi.x);
            s.x = (v > V_TH) ? 1.0f : 0.0f;
            v = fmaf(s.x, -V_TH, v);

            v = fmaf(v, DECAY, xi.y);
            s.y = (v > V_TH) ? 1.0f : 0.0f;
            v = fmaf(s.y, -V_TH, v);

            v = fmaf(v, DECAY, xi.z);
            s.z = (v > V_TH) ? 1.0f : 0.0f;
            v = fmaf(s.z, -V_TH, v);

            v = fmaf(v, DECAY, xi.w);
            s.w = (v > V_TH) ? 1.0f : 0.0f;
            v = fmaf(s.w, -V_TH, v);

            *reinterpret_cast<float4*>(&rowp[i * 4]) = s;
        }
    }
    __syncthreads();

    // Phase 3: coalesced store.
#pragma unroll
    for (int k = 0; k < N4; ++k) {
        int fidx = tid + k * ROWS_PER_CTA;
        int r = fidx / N4;
        int c = fidx % N4;
        float4 s = *reinterpret_cast<const float4*>(&tile[r * STRIDE_F + c * 4]);
        gdst[(size_t)r * T4 + BASE4 + c] = s;
    }
    __syncthreads();   // tile reused by next chunk
}

__global__ __launch_bounds__(ROWS_PER_CTA, 16) void lif_kernel(
    const float* __restrict__ x,
    float* __restrict__ out,
    int rows)
{
    __shared__ float tile[ROWS_PER_CTA * STRIDE_F];   // 13312 B

    const int tid = threadIdx.x;
    const int row0 = blockIdx.x * ROWS_PER_CTA;

    const float4* __restrict__ gsrc =
        reinterpret_cast<const float4*>(x + (size_t)row0 * T);
    float4* __restrict__ gdst =
        reinterpret_cast<float4*>(out + (size_t)row0 * T);

    float v = 0.0f;
    process_chunk<13, 0>(gsrc, gdst, tile, tid, v);   // t in [0, 52)
    process_chunk<12, 13>(gsrc, gdst, tile, tid, v);  // t in [52, 100)
}

extern "C" void kernel_launch(void* const* d_in, const int* in_sizes, int n_in,
                              void* d_out, int out_size)
{
    const float* x = (const float*)d_in[0];
    float* out = (float*)d_out;

    int rows = in_sizes[0] / T;                 // 524288
    int blocks = rows / ROWS_PER_CTA;           // 8192
    lif_kernel<<<blocks, ROWS_PER_CTA>>>(x, out, rows);
}